// round 2
// baseline (speedup 1.0000x reference)
#include <cuda_runtime.h>

#define D_CH 20
#define GV 128
#define NUM_EMB (GV * GV * GV)

__global__ void __launch_bounds__(256) dense_grid_enc_kernel(
    const float* __restrict__ x,
    const float* __restrict__ grid,
    float* __restrict__ out,
    int n_pts)
{
    unsigned int gid = blockIdx.x * 256u + threadIdx.x;
    unsigned int total = (unsigned int)n_pts * D_CH;
    if (gid >= total) return;

    unsigned int p = gid / D_CH;
    unsigned int c = gid - p * D_CH;

    float px = __ldg(&x[p * 3 + 0]);
    float py = __ldg(&x[p * 3 + 1]);
    float pz = __ldg(&x[p * 3 + 2]);

    // gp = floor((x - lo)/len * V)   with lo=-1, len=2, V=128
    float tx = (px + 1.0f) * 0.5f * (float)GV;
    float ty = (py + 1.0f) * 0.5f * (float)GV;
    float tz = (pz + 1.0f) * 0.5f * (float)GV;
    int gx = (int)floorf(tx);
    int gy = (int)floorf(ty);
    int gz = (int)floorf(tz);

    // Q_pos corner coords exactly as the reference computes them:
    // pos = idx / V * 2 - 1 ;  denominator (x2-x1) == 2/128 exact -> multiply by 64
    const float inv_v2 = 2.0f / (float)GV;   // exact in fp32
    float x1 = (float)gx * inv_v2 - 1.0f;
    float x2 = (float)(gx + 1) * inv_v2 - 1.0f;
    float y1 = (float)gy * inv_v2 - 1.0f;
    float y2 = (float)(gy + 1) * inv_v2 - 1.0f;
    float z1 = (float)gz * inv_v2 - 1.0f;
    float z2 = (float)(gz + 1) * inv_v2 - 1.0f;

    const float inv_den = 64.0f;             // 1 / (2/128), exact
    float wx0 = (x2 - px) * inv_den;
    float wx1 = (px - x1) * inv_den;
    float wy0 = (y2 - py) * inv_den;
    float wy1 = (py - y1) * inv_den;
    float wz0 = (z2 - pz) * inv_den;
    float wz1 = (pz - z1) * inv_den;

    // flat = gx + gy*V + gz*V*V  (+offsets), clamped like JAX's default gather clip
    int base = gx + gy * GV + gz * GV * GV;
    int f000 = base;
    int f100 = base + 1;
    int f010 = base + GV;
    int f110 = base + GV + 1;
    int f001 = base + GV * GV;
    int f101 = base + GV * GV + 1;
    int f011 = base + GV * GV + GV;
    int f111 = base + GV * GV + GV + 1;

    const int maxi = NUM_EMB - 1;
    f000 = min(f000, maxi);
    f100 = min(f100, maxi);
    f010 = min(f010, maxi);
    f110 = min(f110, maxi);
    f001 = min(f001, maxi);
    f101 = min(f101, maxi);
    f011 = min(f011, maxi);
    f111 = min(f111, maxi);

    float q000 = __ldg(&grid[(size_t)f000 * D_CH + c]);
    float q100 = __ldg(&grid[(size_t)f100 * D_CH + c]);
    float q010 = __ldg(&grid[(size_t)f010 * D_CH + c]);
    float q110 = __ldg(&grid[(size_t)f110 * D_CH + c]);
    float q001 = __ldg(&grid[(size_t)f001 * D_CH + c]);
    float q101 = __ldg(&grid[(size_t)f101 * D_CH + c]);
    float q011 = __ldg(&grid[(size_t)f011 * D_CH + c]);
    float q111 = __ldg(&grid[(size_t)f111 * D_CH + c]);

    float fx0 = wx0 * q000 + wx1 * q100;
    float fx1 = wx0 * q010 + wx1 * q110;
    float fx2 = wx0 * q001 + wx1 * q101;
    float fx3 = wx0 * q011 + wx1 * q111;

    float fy0 = wy0 * fx0 + wy1 * fx1;
    float fy1 = wy0 * fx2 + wy1 * fx3;

    out[gid] = wz0 * fy0 + wz1 * fy1;
}

extern "C" void kernel_launch(void* const* d_in, const int* in_sizes, int n_in,
                              void* d_out, int out_size)
{
    const float* x    = (const float*)d_in[0];
    const float* grid = (const float*)d_in[1];
    float* out        = (float*)d_out;

    int n_pts = in_sizes[0] / 3;
    unsigned int total = (unsigned int)n_pts * D_CH;
    unsigned int blocks = (total + 255u) / 256u;

    dense_grid_enc_kernel<<<blocks, 256>>>(x, grid, out, n_pts);
}

// round 3
// speedup vs baseline: 1.3449x; 1.3449x over previous
#include <cuda_runtime.h>

#define D_CH 20
#define GV 128
#define NUM_EMB (GV * GV * GV)

__global__ void __launch_bounds__(256) dense_grid_enc_v4_kernel(
    const float* __restrict__ x,
    const float* __restrict__ grid,
    float* __restrict__ out,
    int n_pts)
{
    unsigned int gid = blockIdx.x * 256u + threadIdx.x;
    unsigned int total = (unsigned int)n_pts * 5u;   // 5 threads/point, 4 channels each
    if (gid >= total) return;

    unsigned int p  = gid / 5u;
    unsigned int c4 = gid - p * 5u;                  // 0..4
    unsigned int cbase = c4 * 4u;                    // channel offset 0,4,8,12,16

    float px = __ldg(&x[p * 3 + 0]);
    float py = __ldg(&x[p * 3 + 1]);
    float pz = __ldg(&x[p * 3 + 2]);

    float tx = (px + 1.0f) * 0.5f * (float)GV;
    float ty = (py + 1.0f) * 0.5f * (float)GV;
    float tz = (pz + 1.0f) * 0.5f * (float)GV;
    int gx = (int)floorf(tx);
    int gy = (int)floorf(ty);
    int gz = (int)floorf(tz);

    // Corner positions exactly as the reference computes them (idx/V*2 - 1).
    const float inv_v2 = 2.0f / (float)GV;           // exact in fp32
    float x1 = (float)gx * inv_v2 - 1.0f;
    float x2 = (float)(gx + 1) * inv_v2 - 1.0f;
    float y1 = (float)gy * inv_v2 - 1.0f;
    float y2 = (float)(gy + 1) * inv_v2 - 1.0f;
    float z1 = (float)gz * inv_v2 - 1.0f;
    float z2 = (float)(gz + 1) * inv_v2 - 1.0f;

    const float inv_den = 64.0f;                     // 1/(2/128), exact
    float wx0 = (x2 - px) * inv_den;
    float wx1 = (px - x1) * inv_den;
    float wy0 = (y2 - py) * inv_den;
    float wy1 = (py - y1) * inv_den;
    float wz0 = (z2 - pz) * inv_den;
    float wz1 = (pz - z1) * inv_den;

    // flat = gx + gy*V + gz*V*V (+offsets), clamped like JAX's default gather clip
    int base = gx + gy * GV + gz * GV * GV;
    const int maxi = NUM_EMB - 1;
    int f000 = min(base,                maxi);
    int f100 = min(base + 1,            maxi);
    int f010 = min(base + GV,           maxi);
    int f110 = min(base + GV + 1,       maxi);
    int f001 = min(base + GV*GV,        maxi);
    int f101 = min(base + GV*GV + 1,    maxi);
    int f011 = min(base + GV*GV + GV,   maxi);
    int f111 = min(base + GV*GV + GV+1, maxi);

    // Rows are 80 B (16 B aligned) -> float4 loads are legal at flat*20 + cbase
    const float4* g4 = (const float4*)grid;
    // element index flat*20+cbase is divisible by 4: flat*20 %4==0, cbase%4==0
    float4 q000 = __ldg(&g4[((size_t)f000 * D_CH + cbase) >> 2]);
    float4 q100 = __ldg(&g4[((size_t)f100 * D_CH + cbase) >> 2]);
    float4 q010 = __ldg(&g4[((size_t)f010 * D_CH + cbase) >> 2]);
    float4 q110 = __ldg(&g4[((size_t)f110 * D_CH + cbase) >> 2]);
    float4 q001 = __ldg(&g4[((size_t)f001 * D_CH + cbase) >> 2]);
    float4 q101 = __ldg(&g4[((size_t)f101 * D_CH + cbase) >> 2]);
    float4 q011 = __ldg(&g4[((size_t)f011 * D_CH + cbase) >> 2]);
    float4 q111 = __ldg(&g4[((size_t)f111 * D_CH + cbase) >> 2]);

    float4 r;
    {
        float fx0 = wx0 * q000.x + wx1 * q100.x;
        float fx1 = wx0 * q010.x + wx1 * q110.x;
        float fx2 = wx0 * q001.x + wx1 * q101.x;
        float fx3 = wx0 * q011.x + wx1 * q111.x;
        r.x = wz0 * (wy0 * fx0 + wy1 * fx1) + wz1 * (wy0 * fx2 + wy1 * fx3);
    }
    {
        float fx0 = wx0 * q000.y + wx1 * q100.y;
        float fx1 = wx0 * q010.y + wx1 * q110.y;
        float fx2 = wx0 * q001.y + wx1 * q101.y;
        float fx3 = wx0 * q011.y + wx1 * q111.y;
        r.y = wz0 * (wy0 * fx0 + wy1 * fx1) + wz1 * (wy0 * fx2 + wy1 * fx3);
    }
    {
        float fx0 = wx0 * q000.z + wx1 * q100.z;
        float fx1 = wx0 * q010.z + wx1 * q110.z;
        float fx2 = wx0 * q001.z + wx1 * q101.z;
        float fx3 = wx0 * q011.z + wx1 * q111.z;
        r.z = wz0 * (wy0 * fx0 + wy1 * fx1) + wz1 * (wy0 * fx2 + wy1 * fx3);
    }
    {
        float fx0 = wx0 * q000.w + wx1 * q100.w;
        float fx1 = wx0 * q010.w + wx1 * q110.w;
        float fx2 = wx0 * q001.w + wx1 * q101.w;
        float fx3 = wx0 * q011.w + wx1 * q111.w;
        r.w = wz0 * (wy0 * fx0 + wy1 * fx1) + wz1 * (wy0 * fx2 + wy1 * fx3);
    }

    // Output: 5 float4/point = contiguous 80 B, fully coalesced.
    // Streaming store: don't let the write-once output evict grid lines in L2.
    __stcs((float4*)out + gid, r);
}

extern "C" void kernel_launch(void* const* d_in, const int* in_sizes, int n_in,
                              void* d_out, int out_size)
{
    const float* x    = (const float*)d_in[0];
    const float* grid = (const float*)d_in[1];
    float* out        = (float*)d_out;

    int n_pts = in_sizes[0] / 3;
    unsigned int total = (unsigned int)n_pts * 5u;
    unsigned int blocks = (total + 255u) / 256u;

    dense_grid_enc_v4_kernel<<<blocks, 256>>>(x, grid, out, n_pts);
}